// round 12
// baseline (speedup 1.0000x reference)
#include <cuda_runtime.h>
#include <cuda_fp16.h>
#include <cstdint>

#define NSTATE 768
#define BSZ 2
#define SEQ 2048
#define NTOK (BSZ*SEQ)        // 4096
#define NHEAD 12
#define DHEAD 64
#define MSLOTS 100
#define MPAD 128

// ---------------- scratch (device globals; no allocations allowed) ----------------
__device__ float g_qkv[NTOK * 3 * NSTATE];     // [4096, 2304]
__device__ float g_mkv[MSLOTS * 2 * NSTATE];   // [100, 1536]
__device__ float g_a   [NTOK * NSTATE];        // self-attn out
__device__ float g_a1  [NTOK * NSTATE];        // memory-attn out
__device__ float g_fused[NTOK * NSTATE];       // gated fusion
// pre-split fp16 hi/lo transposed weights [N][K]
__device__ __half g_wattnT_h [3*NSTATE*NSTATE];
__device__ __half g_wattnT_l [3*NSTATE*NSTATE];
__device__ __half g_wmemT_h  [2*NSTATE*NSTATE];
__device__ __half g_wmemT_l  [2*NSTATE*NSTATE];
__device__ __half g_walphaT_h[NSTATE*2*NSTATE];
__device__ __half g_walphaT_l[NSTATE*2*NSTATE];
__device__ __half g_wprojT_h [NSTATE*NSTATE];
__device__ __half g_wprojT_l [NSTATE*NSTATE];
// pre-split fp16 hi/lo K and transposed V buffers for attention
__device__ __half g_khi [BSZ*NHEAD*SEQ*DHEAD];   // [b,h,s,d]
__device__ __half g_klo [BSZ*NHEAD*SEQ*DHEAD];
__device__ __half g_vthi[BSZ*NHEAD*DHEAD*SEQ];   // [b,h,d,s]
__device__ __half g_vtlo[BSZ*NHEAD*DHEAD*SEQ];
__device__ __half g_mkhi [NHEAD*MPAD*DHEAD];     // [h,slot,d], zero-padded to 128 slots
__device__ __half g_mklo [NHEAD*MPAD*DHEAD];
__device__ __half g_mvthi[NHEAD*DHEAD*MPAD];     // [h,d,slot]
__device__ __half g_mvtlo[NHEAD*DHEAD*MPAD];

// =================== helpers (compute_103-safe only) ===================
__device__ __forceinline__ uint32_t smem_u32(const void* p){
    uint32_t a;
    asm("{ .reg .u64 t; cvta.to.shared.u64 t, %1; cvt.u32.u64 %0, t; }" : "=r"(a) : "l"(p));
    return a;
}
__device__ __forceinline__ void cp16h(uint32_t dst, const __half* src){
    asm volatile("cp.async.cg.shared.global [%0], [%1], 16;" :: "r"(dst), "l"(src));
}
template<int N> __device__ __forceinline__ void cp_wait(){
    asm volatile("cp.async.wait_group %0;" :: "n"(N) : "memory");
}
__device__ __forceinline__ void cp_commit(){
    asm volatile("cp.async.commit_group;" ::: "memory");
}
__device__ __forceinline__ void mma_f16(float* d, const uint32_t* a, const uint32_t* b){
    asm volatile("mma.sync.aligned.m16n8k16.row.col.f32.f16.f16.f32 "
        "{%0,%1,%2,%3}, {%4,%5,%6,%7}, {%8,%9}, {%0,%1,%2,%3};"
        : "+f"(d[0]), "+f"(d[1]), "+f"(d[2]), "+f"(d[3])
        : "r"(a[0]), "r"(a[1]), "r"(a[2]), "r"(a[3]), "r"(b[0]), "r"(b[1]));
}
// split (x,y) into packed half2 hi and half2 lo (residual)
__device__ __forceinline__ void split2h(float x, float y, uint32_t& hi, uint32_t& lo){
    __half hx = __float2half_rn(x);
    __half hy = __float2half_rn(y);
    __half lx = __float2half_rn(x - __half2float(hx));
    __half ly = __float2half_rn(y - __half2float(hy));
    hi = (uint32_t)__half_as_ushort(hx) | ((uint32_t)__half_as_ushort(hy) << 16);
    lo = (uint32_t)__half_as_ushort(lx) | ((uint32_t)__half_as_ushort(ly) << 16);
}
__device__ __forceinline__ void split1h(float x, __half& hi, __half& lo){
    hi = __float2half_rn(x);
    lo = __float2half_rn(x - __half2float(hi));
}

// =================== weight transpose+split: src[K][N] -> hi/lo half [N][K] ===================
__global__ __launch_bounds__(256)
void transpose_kh(const float* __restrict__ src, __half* __restrict__ dhi,
                  __half* __restrict__ dlo, int K, int N)
{
    __shared__ float tile[32][33];
    const int tx = threadIdx.x, ty = threadIdx.y;
    const int n0 = blockIdx.x * 32, k0 = blockIdx.y * 32;
    #pragma unroll
    for (int r = 0; r < 4; r++)
        tile[ty + r*8][tx] = src[(size_t)(k0 + ty + r*8) * N + n0 + tx];
    __syncthreads();
    #pragma unroll
    for (int r = 0; r < 4; r++) {
        float v = tile[tx][ty + r*8];
        __half hi, lo; split1h(v, hi, lo);
        size_t dst = (size_t)(n0 + ty + r*8) * K + k0 + tx;
        dhi[dst] = hi;
        dlo[dst] = lo;
    }
}

// =================== K prep: qkv K-part -> khi/klo [b,h,s,d] half ===================
__global__ __launch_bounds__(256)
void prep_k(const float* __restrict__ qkv, __half* __restrict__ khi, __half* __restrict__ klo)
{
    int idx = blockIdx.x * 256 + threadIdx.x;        // one float4
    int flat = idx * 4;                               // element in [NTOK x 768]
    int tok = flat / NSTATE;
    int c   = flat - tok * NSTATE;
    float4 v = *(const float4*)(qkv + (size_t)tok * (3*NSTATE) + NSTATE + c);
    int b = tok >> 11, s = tok & 2047;
    int h = c >> 6,  d = c & 63;
    size_t dst = (((size_t)(b*NHEAD + h) * SEQ) + s) * DHEAD + d;
    __half h0,l0,h1,l1,h2,l2,h3,l3;
    split1h(v.x,h0,l0); split1h(v.y,h1,l1); split1h(v.z,h2,l2); split1h(v.w,h3,l3);
    ushort4 hv = make_ushort4(__half_as_ushort(h0),__half_as_ushort(h1),__half_as_ushort(h2),__half_as_ushort(h3));
    ushort4 lv = make_ushort4(__half_as_ushort(l0),__half_as_ushort(l1),__half_as_ushort(l2),__half_as_ushort(l3));
    *(ushort4*)(khi + dst) = hv;
    *(ushort4*)(klo + dst) = lv;
}

// =================== V prep: qkv V-part -> transposed vthi/vtlo [b,h,d,s] half ===================
__global__ __launch_bounds__(256)
void prep_vt(const float* __restrict__ qkv, __half* __restrict__ vthi, __half* __restrict__ vtlo)
{
    __shared__ float tile[32][33];
    const int tx = threadIdx.x, ty = threadIdx.y;
    const int s0 = blockIdx.x * 32, d0 = blockIdx.y * 32;
    const int bh = blockIdx.z;                       // b*NHEAD + h
    const int b = bh / NHEAD, h = bh - b * NHEAD;
    #pragma unroll
    for (int r = 0; r < 4; r++) {
        int s = s0 + ty + r*8;
        tile[ty + r*8][tx] = qkv[((size_t)(b*SEQ + s)) * (3*NSTATE) + 2*NSTATE + h*64 + d0 + tx];
    }
    __syncthreads();
    #pragma unroll
    for (int r = 0; r < 4; r++) {
        int d = d0 + ty + r*8;
        float v = tile[tx][ty + r*8];
        __half hi, lo; split1h(v, hi, lo);
        size_t dst = ((size_t)(bh*DHEAD + d)) * SEQ + s0 + tx;
        vthi[dst] = hi;
        vtlo[dst] = lo;
    }
}

// =================== memory-KV prep (tiny, zero-padded to 128 slots) ===================
__global__ __launch_bounds__(256)
void prep_m(const float* __restrict__ mkv,
            __half* __restrict__ mkhi, __half* __restrict__ mklo,
            __half* __restrict__ mvthi, __half* __restrict__ mvtlo)
{
    int idx = blockIdx.x * 256 + threadIdx.x;        // over NHEAD*MPAD*DHEAD
    if (idx >= NHEAD*MPAD*DHEAD) return;
    int h = idx / (MPAD*DHEAD);
    int r = idx - h * (MPAD*DHEAD);
    int slot = r >> 6, d = r & 63;
    float kvl = (slot < MSLOTS) ? mkv[(size_t)slot * (2*NSTATE) + h*64 + d] : 0.f;
    float vvl = (slot < MSLOTS) ? mkv[(size_t)slot * (2*NSTATE) + NSTATE + h*64 + d] : 0.f;
    __half khf, klf, vhf, vlf;
    split1h(kvl, khf, klf);
    split1h(vvl, vhf, vlf);
    mkhi[(size_t)(h*MPAD + slot)*DHEAD + d] = khf;
    mklo[(size_t)(h*MPAD + slot)*DHEAD + d] = klf;
    mvthi[(size_t)(h*DHEAD + d)*MPAD + slot] = vhf;
    mvtlo[(size_t)(h*DHEAD + d)*MPAD + slot] = vlf;
}

// =================== fp16 split-3 GEMM (m16n8k16): C[M,N] = A @ BtT + bias ===================
// A fp32 (split at STS); Bt pre-split fp16 hi/lo [N][K]. BM=BN=128, BK=32.
// 8 warps 2(m)x4(n); warp 64x32 via 4x4 m16n8k16 tiles, 2 k-steps per ktile, 3 MMAs per tile.
// smem words (uint32): A_hi b*2304, A_lo 4608+b*2304, B_hi 9216+b*2304, B_lo 13824+b*2304.
// Row layout: 18 words/row (16 half2 data + 2 pad). Epilogue reuses smem as 128x132 floats.
// MODE 0: C = A@B + bias ;  MODE 1: A=concat(A,A2)@ksplit, C = eb + sigmoid(acc+bias)*(ea-eb)
template<int MODE>
__global__ __launch_bounds__(256)
void gemm_h16(const float* __restrict__ A, const float* __restrict__ A2,
              const __half* __restrict__ Bthi, const __half* __restrict__ Btlo,
              const float* __restrict__ bias,
              float* __restrict__ C, const float* __restrict__ ea, const float* __restrict__ eb,
              int M, int N, int K, int lda, int ksplit)
{
    extern __shared__ char smem[];
    uint32_t* usm = (uint32_t*)smem;
    const int tid = threadIdx.x;
    const int w = tid >> 5, lane = tid & 31;
    const int lr = lane >> 2, kc = lane & 3;
    const int warp_m = (w >> 2) * 64;
    const int warp_n = (w & 3) * 32;
    const int row0 = blockIdx.y * 128, col0 = blockIdx.x * 128;

    const int T = K >> 5;
    const int arow = tid >> 1;           // 0..127
    const int acol0 = (tid & 1) * 16;    // 0 or 16 (elements)
    const bool aval = (row0 + arow) < M;

    float4 pa[4];
    uint4 pbh[2], pbl[2];
    auto ldg = [&](int t){
        int k0 = t * 32;
        const float* As; int ka;
        if (MODE == 1 && k0 >= ksplit) { As = A2; ka = k0 - ksplit; } else { As = A; ka = k0; }
        const float* asrc = As + (size_t)(row0 + arow) * lda + ka + acol0;
        const __half* bh = Bthi + (size_t)(col0 + arow) * K + k0 + acol0;
        const __half* bl = Btlo + (size_t)(col0 + arow) * K + k0 + acol0;
        #pragma unroll
        for (int j = 0; j < 4; j++)
            pa[j] = aval ? *(const float4*)(asrc + 4*j) : make_float4(0.f,0.f,0.f,0.f);
        pbh[0] = *(const uint4*)bh;  pbh[1] = *(const uint4*)(bh + 8);
        pbl[0] = *(const uint4*)bl;  pbl[1] = *(const uint4*)(bl + 8);
    };
    auto sts = [&](int b){
        const int base = arow * 18 + (acol0 >> 1);
        uint32_t* dah = usm + b * 2304 + base;
        uint32_t* dal = usm + 4608 + b * 2304 + base;
        uint32_t* dbh = usm + 9216 + b * 2304 + base;
        uint32_t* dbl = usm + 13824 + b * 2304 + base;
        uint32_t ah[8], al[8];
        #pragma unroll
        for (int j = 0; j < 4; j++) {
            split2h(pa[j].x, pa[j].y, ah[2*j],   al[2*j]);
            split2h(pa[j].z, pa[j].w, ah[2*j+1], al[2*j+1]);
        }
        #pragma unroll
        for (int j = 0; j < 4; j++) {
            *(uint2*)(dah + 2*j) = make_uint2(ah[2*j], ah[2*j+1]);
            *(uint2*)(dal + 2*j) = make_uint2(al[2*j], al[2*j+1]);
        }
        *(uint2*)(dbh)     = make_uint2(pbh[0].x, pbh[0].y);
        *(uint2*)(dbh + 2) = make_uint2(pbh[0].z, pbh[0].w);
        *(uint2*)(dbh + 4) = make_uint2(pbh[1].x, pbh[1].y);
        *(uint2*)(dbh + 6) = make_uint2(pbh[1].z, pbh[1].w);
        *(uint2*)(dbl)     = make_uint2(pbl[0].x, pbl[0].y);
        *(uint2*)(dbl + 2) = make_uint2(pbl[0].z, pbl[0].w);
        *(uint2*)(dbl + 4) = make_uint2(pbl[1].x, pbl[1].y);
        *(uint2*)(dbl + 6) = make_uint2(pbl[1].z, pbl[1].w);
    };

    float acc[4][4][4];
    #pragma unroll
    for (int i = 0; i < 4; i++)
        #pragma unroll
        for (int j = 0; j < 4; j++)
            #pragma unroll
            for (int r = 0; r < 4; r++) acc[i][j][r] = 0.f;

    ldg(0); sts(0);
    if (T > 1) ldg(1);
    __syncthreads();

    for (int t = 0; t < T; ++t) {
        int b = t & 1;
        const uint32_t* Ah = usm + b * 2304;
        const uint32_t* Al = usm + 4608 + b * 2304;
        const uint32_t* Bh = usm + 9216 + b * 2304;
        const uint32_t* Bl = usm + 13824 + b * 2304;
        #pragma unroll
        for (int s = 0; s < 2; s++) {
            const int kb = s * 8 + kc;
            uint32_t afh[4][4], afl[4][4], bfh[4][2], bfl[4][2];
            #pragma unroll
            for (int i = 0; i < 4; i++) {
                int r0 = (warp_m + i * 16 + lr) * 18;
                afh[i][0] = Ah[r0 + kb];          afl[i][0] = Al[r0 + kb];
                afh[i][1] = Ah[r0 + 8*18 + kb];   afl[i][1] = Al[r0 + 8*18 + kb];
                afh[i][2] = Ah[r0 + kb + 4];      afl[i][2] = Al[r0 + kb + 4];
                afh[i][3] = Ah[r0 + 8*18 + kb+4]; afl[i][3] = Al[r0 + 8*18 + kb+4];
            }
            #pragma unroll
            for (int j = 0; j < 4; j++) {
                int c0 = (warp_n + j * 8 + lr) * 18;
                bfh[j][0] = Bh[c0 + kb];     bfh[j][1] = Bh[c0 + kb + 4];
                bfl[j][0] = Bl[c0 + kb];     bfl[j][1] = Bl[c0 + kb + 4];
            }
            #pragma unroll
            for (int i = 0; i < 4; i++)
                #pragma unroll
                for (int j = 0; j < 4; j++) {
                    mma_f16(acc[i][j], afh[i], bfh[j]);
                    mma_f16(acc[i][j], afl[i], bfh[j]);
                    mma_f16(acc[i][j], afh[i], bfl[j]);
                }
        }
        if (t + 1 < T) {
            sts(b ^ 1);
            if (t + 2 < T) ldg(t + 2);
        }
        __syncthreads();
    }

    // ---- epilogue: regs -> smem stage -> coalesced STG with bias / gate ----
    float* st = (float*)smem;    // 128 x 132 floats
    #pragma unroll
    for (int i = 0; i < 4; i++) {
        #pragma unroll
        for (int j = 0; j < 4; j++) {
            int row = warp_m + i * 16 + lr;
            int col = warp_n + j * 8 + 2 * kc;
            *(float2*)&st[row * 132 + col]       = make_float2(acc[i][j][0], acc[i][j][1]);
            *(float2*)&st[(row + 8) * 132 + col] = make_float2(acc[i][j][2], acc[i][j][3]);
        }
    }
    __syncthreads();
    {
        int r  = tid >> 1;
        int ch = (tid & 1) * 64;
        int grow = row0 + r;
        if (grow < M) {
            #pragma unroll
            for (int c4 = 0; c4 < 16; c4++) {
                int col = ch + c4 * 4;
                float4 v  = *(float4*)&st[r * 132 + col];
                float4 bv = *(const float4*)(bias + col0 + col);
                v.x += bv.x; v.y += bv.y; v.z += bv.z; v.w += bv.w;
                size_t idx = (size_t)grow * N + col0 + col;
                if (MODE == 1) {
                    float4 av  = *(const float4*)(ea + idx);
                    float4 a1v = *(const float4*)(eb + idx);
                    float4 o; float al;
                    al = 1.f/(1.f + __expf(-v.x)); o.x = a1v.x + al*(av.x - a1v.x);
                    al = 1.f/(1.f + __expf(-v.y)); o.y = a1v.y + al*(av.y - a1v.y);
                    al = 1.f/(1.f + __expf(-v.z)); o.z = a1v.z + al*(av.z - a1v.z);
                    al = 1.f/(1.f + __expf(-v.w)); o.w = a1v.w + al*(av.w - a1v.w);
                    *(float4*)(C + idx) = o;
                } else {
                    *(float4*)(C + idx) = v;
                }
            }
        }
    }
}

// =================== fp16 split-3 flash attention, pre-split K/V via cp.async (R11, verified) ===================
__global__ __launch_bounds__(256, 2)
void attn_h16(const float* __restrict__ qbase,
              const __half* __restrict__ khi, const __half* __restrict__ klo,
              const __half* __restrict__ vthi, const __half* __restrict__ vtlo,
              float* __restrict__ outbuf,
              int kv_len, int kslots, int q_stride, long long q_bstride, int kv_batched)
{
    extern __shared__ uint32_t sm4[];
    uint32_t* Khi = sm4;                 // [64][36] words
    uint32_t* Klo = sm4 + 64*36;
    uint32_t* Vhi = sm4 + 2*64*36;       // [d=64][36] words (half2 over key pairs)
    uint32_t* Vlo = sm4 + 3*64*36;
    const uint32_t sb = smem_u32(sm4);

    const int tid = threadIdx.x;
    const int w = tid >> 5, lane = tid & 31;
    const int lr = lane >> 2, kc = lane & 3;
    const int h = blockIdx.y, b = blockIdx.z;
    const int q0 = blockIdx.x * 128;
    const float* qb = qbase + (size_t)b * q_bstride + h * 64;
    const int bh = kv_batched * b * NHEAD + h;
    const __half* kbh = khi  + (size_t)bh * kslots * DHEAD;
    const __half* kbl = klo  + (size_t)bh * kslots * DHEAD;
    const __half* vbh = vthi + (size_t)bh * DHEAD * kslots;
    const __half* vbl = vtlo + (size_t)bh * DHEAD * kslots;

    const int qrow0 = q0 + w * 16 + lr;

    uint32_t Qh[4][4], Ql[4][4];
    {
        const float* r0p = qb + (size_t)qrow0 * q_stride;
        const float* r1p = qb + (size_t)(qrow0 + 8) * q_stride;
        #pragma unroll
        for (int c = 0; c < 4; c++) {
            int d0 = c * 16 + 2 * kc;
            float2 v00 = *(const float2*)(r0p + d0);
            float2 v10 = *(const float2*)(r1p + d0);
            float2 v01 = *(const float2*)(r0p + d0 + 8);
            float2 v11 = *(const float2*)(r1p + d0 + 8);
            split2h(v00.x, v00.y, Qh[c][0], Ql[c][0]);
            split2h(v10.x, v10.y, Qh[c][1], Ql[c][1]);
            split2h(v01.x, v01.y, Qh[c][2], Ql[c][2]);
            split2h(v11.x, v11.y, Qh[c][3], Ql[c][3]);
        }
    }

    float m0 = -1e30f, m1 = -1e30f, l0 = 0.f, l1 = 0.f;
    float O[8][4];
    #pragma unroll
    for (int d = 0; d < 8; d++) { O[d][0]=0.f; O[d][1]=0.f; O[d][2]=0.f; O[d][3]=0.f; }

    const int ldrow = tid >> 2;
    const int ldseg = (tid & 3) * 2;
    const uint32_t soff = (uint32_t)ldrow * 144u + (uint32_t)ldseg * 16u;

    const int nkb = (kv_len + 63) >> 6;
    for (int t = 0; t < nkb; ++t) {
        __syncthreads();
        {
            size_t goff = ((size_t)(t*64 + ldrow)) * DHEAD + ldseg * 8;
            size_t voff = ((size_t)ldrow) * kslots + (size_t)t*64 + ldseg * 8;
            cp16h(sb + soff,                    kbh + goff);
            cp16h(sb + soff + 16,               kbh + goff + 8);
            cp16h(sb + 9216u  + soff,           kbl + goff);
            cp16h(sb + 9216u  + soff + 16,      kbl + goff + 8);
            cp16h(sb + 18432u + soff,           vbh + voff);
            cp16h(sb + 18432u + soff + 16,      vbh + voff + 8);
            cp16h(sb + 27648u + soff,           vbl + voff);
            cp16h(sb + 27648u + soff + 16,      vbl + voff + 8);
            cp_commit();
        }
        cp_wait<0>();
        __syncthreads();

        // ---- S = Q K^T (fp16 split-3) ----
        float sD[8][4];
        #pragma unroll
        for (int nt = 0; nt < 8; nt++) {
            float d4[4] = {0.f, 0.f, 0.f, 0.f};
            const int base = (8*nt + lr) * 36 + kc;
            #pragma unroll
            for (int c = 0; c < 4; c++) {
                uint32_t bh2[2], bl2[2];
                bh2[0] = Khi[base + 8*c];  bh2[1] = Khi[base + 8*c + 4];
                bl2[0] = Klo[base + 8*c];  bl2[1] = Klo[base + 8*c + 4];
                mma_f16(d4, Qh[c], bh2);
                mma_f16(d4, Ql[c], bh2);
                mma_f16(d4, Qh[c], bl2);
            }
            sD[nt][0]=d4[0]; sD[nt][1]=d4[1]; sD[nt][2]=d4[2]; sD[nt][3]=d4[3];
        }

        int rem = kv_len - t * 64;
        if (rem < 64) {
            #pragma unroll
            for (int nt = 0; nt < 8; nt++) {
                int k0e = 8*nt + 2*kc;
                if (k0e     >= rem) { sD[nt][0] = -1e30f; sD[nt][2] = -1e30f; }
                if (k0e + 1 >= rem) { sD[nt][1] = -1e30f; sD[nt][3] = -1e30f; }
            }
        }

        float rm0 = -1e30f, rm1 = -1e30f;
        #pragma unroll
        for (int nt = 0; nt < 8; nt++) {
            rm0 = fmaxf(rm0, fmaxf(sD[nt][0], sD[nt][1]));
            rm1 = fmaxf(rm1, fmaxf(sD[nt][2], sD[nt][3]));
        }
        rm0 = fmaxf(rm0, __shfl_xor_sync(0xffffffffu, rm0, 1));
        rm0 = fmaxf(rm0, __shfl_xor_sync(0xffffffffu, rm0, 2));
        rm1 = fmaxf(rm1, __shfl_xor_sync(0xffffffffu, rm1, 1));
        rm1 = fmaxf(rm1, __shfl_xor_sync(0xffffffffu, rm1, 2));
        float mn0 = fmaxf(m0, rm0), mn1 = fmaxf(m1, rm1);
        float sc0 = __expf(m0 - mn0), sc1 = __expf(m1 - mn1);
        m0 = mn0; m1 = mn1;
        float rs0 = 0.f, rs1 = 0.f;
        #pragma unroll
        for (int nt = 0; nt < 8; nt++) {
            sD[nt][0] = __expf(sD[nt][0] - m0);
            sD[nt][1] = __expf(sD[nt][1] - m0);
            sD[nt][2] = __expf(sD[nt][2] - m1);
            sD[nt][3] = __expf(sD[nt][3] - m1);
            rs0 += sD[nt][0] + sD[nt][1];
            rs1 += sD[nt][2] + sD[nt][3];
        }
        rs0 += __shfl_xor_sync(0xffffffffu, rs0, 1);
        rs0 += __shfl_xor_sync(0xffffffffu, rs0, 2);
        rs1 += __shfl_xor_sync(0xffffffffu, rs1, 1);
        rs1 += __shfl_xor_sync(0xffffffffu, rs1, 2);
        l0 = l0 * sc0 + rs0;
        l1 = l1 * sc1 + rs1;
        #pragma unroll
        for (int d = 0; d < 8; d++) {
            O[d][0] *= sc0; O[d][1] *= sc0; O[d][2] *= sc1; O[d][3] *= sc1;
        }

        // ---- O += P V (fp16 split-3); QK D-frag == PV A-frag layout, no shuffles ----
        #pragma unroll
        for (int c = 0; c < 4; c++) {
            uint32_t aH[4], aL[4];
            split2h(sD[2*c][0],   sD[2*c][1],   aH[0], aL[0]);
            split2h(sD[2*c][2],   sD[2*c][3],   aH[1], aL[1]);
            split2h(sD[2*c+1][0], sD[2*c+1][1], aH[2], aL[2]);
            split2h(sD[2*c+1][2], sD[2*c+1][3], aH[3], aL[3]);
            #pragma unroll
            for (int dt = 0; dt < 8; dt++) {
                const int base = (8*dt + lr) * 36 + 8*c + kc;
                uint32_t bh2[2], bl2[2];
                bh2[0] = Vhi[base];  bh2[1] = Vhi[base + 4];
                bl2[0] = Vlo[base];  bl2[1] = Vlo[base + 4];
                mma_f16(O[dt], aH, bh2);
                mma_f16(O[dt], aL, bh2);
                mma_f16(O[dt], aH, bl2);
            }
        }
    }

    // ---- epilogue ----
    float inv0 = 1.f / l0, inv1 = 1.f / l1;
    float* op0 = outbuf + ((size_t)b * SEQ + qrow0) * NSTATE + h * 64;
    float* op1 = op0 + 8 * NSTATE;
    #pragma unroll
    for (int dt = 0; dt < 8; dt++) {
        *(float2*)(op0 + dt*8 + 2*kc) = make_float2(O[dt][0]*inv0, O[dt][1]*inv0);
        *(float2*)(op1 + dt*8 + 2*kc) = make_float2(O[dt][2]*inv1, O[dt][3]*inv1);
    }
}

// ------------------------------- launch --------------------------------------------
extern "C" void kernel_launch(void* const* d_in, const int* in_sizes, int n_in,
                              void* d_out, int out_size)
{
    const float* x       = (const float*)d_in[0];
    const float* w_attn  = (const float*)d_in[1];
    const float* b_attn  = (const float*)d_in[2];
    const float* w_proj  = (const float*)d_in[3];
    const float* b_proj  = (const float*)d_in[4];
    const float* w_mem   = (const float*)d_in[5];
    const float* b_mem   = (const float*)d_in[6];
    const float* w_alpha = (const float*)d_in[7];
    const float* b_alpha = (const float*)d_in[8];
    const float* memf    = (const float*)d_in[9];
    float* out = (float*)d_out;

    float *qkv, *mkv, *a, *a1, *fu;
    __half *wah, *wal, *wmh, *wml, *wph, *wpl, *wxh, *wxl;
    __half *khi, *klo, *vthi, *vtlo, *mkhi, *mklo, *mvthi, *mvtlo;
    cudaGetSymbolAddress((void**)&qkv, g_qkv);
    cudaGetSymbolAddress((void**)&mkv, g_mkv);
    cudaGetSymbolAddress((void**)&a,   g_a);
    cudaGetSymbolAddress((void**)&a1,  g_a1);
    cudaGetSymbolAddress((void**)&fu,  g_fused);
    cudaGetSymbolAddress((void**)&wah, g_wattnT_h);
    cudaGetSymbolAddress((void**)&wal, g_wattnT_l);
    cudaGetSymbolAddress((void**)&wmh, g_wmemT_h);
    cudaGetSymbolAddress((void**)&wml, g_wmemT_l);
    cudaGetSymbolAddress((void**)&wxh, g_walphaT_h);
    cudaGetSymbolAddress((void**)&wxl, g_walphaT_l);
    cudaGetSymbolAddress((void**)&wph, g_wprojT_h);
    cudaGetSymbolAddress((void**)&wpl, g_wprojT_l);
    cudaGetSymbolAddress((void**)&khi,  g_khi);
    cudaGetSymbolAddress((void**)&klo,  g_klo);
    cudaGetSymbolAddress((void**)&vthi, g_vthi);
    cudaGetSymbolAddress((void**)&vtlo, g_vtlo);
    cudaGetSymbolAddress((void**)&mkhi,  g_mkhi);
    cudaGetSymbolAddress((void**)&mklo,  g_mklo);
    cudaGetSymbolAddress((void**)&mvthi, g_mvthi);
    cudaGetSymbolAddress((void**)&mvtlo, g_mvtlo);

    const int attn_smem = 4 * 64 * 36 * 4;     // 36864
    const int gemm_smem = 73728;               // 8 x 2304-word tiles / 128x132 float stage
    cudaFuncSetAttribute(attn_h16, cudaFuncAttributeMaxDynamicSharedMemorySize, attn_smem);
    cudaFuncSetAttribute(gemm_h16<0>, cudaFuncAttributeMaxDynamicSharedMemorySize, gemm_smem);
    cudaFuncSetAttribute(gemm_h16<1>, cudaFuncAttributeMaxDynamicSharedMemorySize, gemm_smem);

    dim3 tb(32, 8);
    // weight transpose + fp16 hi/lo split: src[K][N] -> hi/lo [N][K]
    transpose_kh<<<dim3(3*NSTATE/32, NSTATE/32), tb>>>(w_attn,  wah, wal, NSTATE,   3*NSTATE);
    transpose_kh<<<dim3(2*NSTATE/32, NSTATE/32), tb>>>(w_mem,   wmh, wml, NSTATE,   2*NSTATE);
    transpose_kh<<<dim3(NSTATE/32, 2*NSTATE/32), tb>>>(w_alpha, wxh, wxl, 2*NSTATE, NSTATE);
    transpose_kh<<<dim3(NSTATE/32, NSTATE/32),   tb>>>(w_proj,  wph, wpl, NSTATE,   NSTATE);

    // 1) qkv = x @ w_attn + b_attn      [4096, 2304]
    gemm_h16<0><<<dim3(3*NSTATE/128, NTOK/128), 256, gemm_smem>>>(
        x, nullptr, wah, wal, b_attn, qkv, nullptr, nullptr,
        NTOK, 3*NSTATE, NSTATE, NSTATE, 0);

    // 2) mkv = mem @ w_mem + b_mem      [100, 1536]
    gemm_h16<0><<<dim3(2*NSTATE/128, 1), 256, gemm_smem>>>(
        memf, nullptr, wmh, wml, b_mem, mkv, nullptr, nullptr,
        MSLOTS, 2*NSTATE, NSTATE, NSTATE, 0);

    // 2b) pre-split K/V into fp16 hi/lo buffers
    prep_k<<<NTOK*NSTATE/4/256, 256>>>(qkv, khi, klo);
    prep_vt<<<dim3(SEQ/32, DHEAD/32, BSZ*NHEAD), tb>>>(qkv, vthi, vtlo);
    prep_m<<<(NHEAD*MPAD*DHEAD + 255)/256, 256>>>(mkv, mkhi, mklo, mvthi, mvtlo);

    // 3) self attention -> g_a
    attn_h16<<<dim3(SEQ/128, NHEAD, BSZ), 256, attn_smem>>>(
        qkv, khi, klo, vthi, vtlo, a,
        SEQ, SEQ, 3*NSTATE, (long long)SEQ * 3 * NSTATE, 1);

    // 4) memory attention -> g_a1 (kv shared across batch)
    attn_h16<<<dim3(SEQ/128, NHEAD, BSZ), 256, attn_smem>>>(
        qkv, mkhi, mklo, mvthi, mvtlo, a1,
        MSLOTS, MPAD, 3*NSTATE, (long long)SEQ * 3 * NSTATE, 0);

    // 5) fused = sigmoid([a|a1]@w_alpha + b_alpha) gate
    gemm_h16<1><<<dim3(NSTATE/128, NTOK/128), 256, gemm_smem>>>(
        a, a1, wxh, wxl, b_alpha, fu, a, a1,
        NTOK, NSTATE, 2*NSTATE, NSTATE, NSTATE);

    // 6) out = fused @ w_proj + b_proj
    gemm_h16<0><<<dim3(NSTATE/128, NTOK/128), 256, gemm_smem>>>(
        fu, nullptr, wph, wpl, b_proj, out, nullptr, nullptr,
        NTOK, NSTATE, NSTATE, NSTATE, 0);
}

// round 14
// speedup vs baseline: 1.3086x; 1.3086x over previous
#include <cuda_runtime.h>
#include <cuda_fp16.h>
#include <cstdint>

#define NSTATE 768
#define BSZ 2
#define SEQ 2048
#define NTOK (BSZ*SEQ)        // 4096
#define NHEAD 12
#define DHEAD 64
#define MSLOTS 100
#define MPAD 128

// ---------------- scratch (device globals; no allocations allowed) ----------------
__device__ float g_qkv[NTOK * 3 * NSTATE];     // [4096, 2304]
__device__ float g_mkv[MSLOTS * 2 * NSTATE];   // [100, 1536]
__device__ float g_a   [NTOK * NSTATE];        // self-attn out
__device__ float g_a1  [NTOK * NSTATE];        // memory-attn out
__device__ float g_fused[NTOK * NSTATE];       // gated fusion
// transposed weights (K-major, N-major rows: Bt[n][k])
__device__ float g_wattnT [3*NSTATE*NSTATE];
__device__ float g_wmemT  [2*NSTATE*NSTATE];
__device__ float g_walphaT[NSTATE*2*NSTATE];
__device__ float g_wprojT [NSTATE*NSTATE];
// pre-split fp16 hi/lo K and transposed V buffers for attention
__device__ __half g_khi [BSZ*NHEAD*SEQ*DHEAD];   // [b,h,s,d]
__device__ __half g_klo [BSZ*NHEAD*SEQ*DHEAD];
__device__ __half g_vthi[BSZ*NHEAD*DHEAD*SEQ];   // [b,h,d,s]
__device__ __half g_vtlo[BSZ*NHEAD*DHEAD*SEQ];
__device__ __half g_mkhi [NHEAD*MPAD*DHEAD];     // [h,slot,d], zero-padded to 128 slots
__device__ __half g_mklo [NHEAD*MPAD*DHEAD];
__device__ __half g_mvthi[NHEAD*DHEAD*MPAD];     // [h,d,slot]
__device__ __half g_mvtlo[NHEAD*DHEAD*MPAD];

// =================== helpers (compute_103-safe only) ===================
__device__ __forceinline__ uint32_t smem_u32(const void* p){
    uint32_t a;
    asm("{ .reg .u64 t; cvta.to.shared.u64 t, %1; cvt.u32.u64 %0, t; }" : "=r"(a) : "l"(p));
    return a;
}
__device__ __forceinline__ void cp16h(uint32_t dst, const __half* src){
    asm volatile("cp.async.cg.shared.global [%0], [%1], 16;" :: "r"(dst), "l"(src));
}
template<int N> __device__ __forceinline__ void cp_wait(){
    asm volatile("cp.async.wait_group %0;" :: "n"(N) : "memory");
}
__device__ __forceinline__ void cp_commit(){
    asm volatile("cp.async.commit_group;" ::: "memory");
}
__device__ __forceinline__ uint32_t f2tf32(float f){
    uint32_t r;
    asm("cvt.rna.tf32.f32 %0, %1;" : "=r"(r) : "f"(f));
    return r;
}
__device__ __forceinline__ void mma_tf32(float* d, const uint32_t* a, const uint32_t* b){
    asm volatile("mma.sync.aligned.m16n8k8.row.col.f32.tf32.tf32.f32 "
        "{%0,%1,%2,%3}, {%4,%5,%6,%7}, {%8,%9}, {%0,%1,%2,%3};"
        : "+f"(d[0]), "+f"(d[1]), "+f"(d[2]), "+f"(d[3])
        : "r"(a[0]), "r"(a[1]), "r"(a[2]), "r"(a[3]), "r"(b[0]), "r"(b[1]));
}
__device__ __forceinline__ void mma_f16(float* d, const uint32_t* a, const uint32_t* b){
    asm volatile("mma.sync.aligned.m16n8k16.row.col.f32.f16.f16.f32 "
        "{%0,%1,%2,%3}, {%4,%5,%6,%7}, {%8,%9}, {%0,%1,%2,%3};"
        : "+f"(d[0]), "+f"(d[1]), "+f"(d[2]), "+f"(d[3])
        : "r"(a[0]), "r"(a[1]), "r"(a[2]), "r"(a[3]), "r"(b[0]), "r"(b[1]));
}
// split (x,y) into packed half2 hi and half2 lo (residual)
__device__ __forceinline__ void split2h(float x, float y, uint32_t& hi, uint32_t& lo){
    __half hx = __float2half_rn(x);
    __half hy = __float2half_rn(y);
    __half lx = __float2half_rn(x - __half2float(hx));
    __half ly = __float2half_rn(y - __half2float(hy));
    hi = (uint32_t)__half_as_ushort(hx) | ((uint32_t)__half_as_ushort(hy) << 16);
    lo = (uint32_t)__half_as_ushort(lx) | ((uint32_t)__half_as_ushort(ly) << 16);
}
__device__ __forceinline__ void split1h(float x, __half& hi, __half& lo){
    hi = __float2half_rn(x);
    lo = __float2half_rn(x - __half2float(hi));
}

// =================== weight transpose: src[K][N] -> dst[N][K] ===================
__global__ __launch_bounds__(256)
void transpose_k(const float* __restrict__ src, float* __restrict__ dst, int K, int N)
{
    __shared__ float tile[32][33];
    const int tx = threadIdx.x, ty = threadIdx.y;
    const int n0 = blockIdx.x * 32, k0 = blockIdx.y * 32;
    #pragma unroll
    for (int r = 0; r < 4; r++)
        tile[ty + r*8][tx] = src[(size_t)(k0 + ty + r*8) * N + n0 + tx];
    __syncthreads();
    #pragma unroll
    for (int r = 0; r < 4; r++)
        dst[(size_t)(n0 + ty + r*8) * K + k0 + tx] = tile[tx][ty + r*8];
}

// =================== K prep: qkv K-part -> khi/klo [b,h,s,d] half ===================
__global__ __launch_bounds__(256)
void prep_k(const float* __restrict__ qkv, __half* __restrict__ khi, __half* __restrict__ klo)
{
    int idx = blockIdx.x * 256 + threadIdx.x;        // one float4
    int flat = idx * 4;                               // element in [NTOK x 768]
    int tok = flat / NSTATE;
    int c   = flat - tok * NSTATE;
    float4 v = *(const float4*)(qkv + (size_t)tok * (3*NSTATE) + NSTATE + c);
    int b = tok >> 11, s = tok & 2047;
    int h = c >> 6,  d = c & 63;
    size_t dst = (((size_t)(b*NHEAD + h) * SEQ) + s) * DHEAD + d;
    __half h0,l0,h1,l1,h2,l2,h3,l3;
    split1h(v.x,h0,l0); split1h(v.y,h1,l1); split1h(v.z,h2,l2); split1h(v.w,h3,l3);
    ushort4 hv = make_ushort4(__half_as_ushort(h0),__half_as_ushort(h1),__half_as_ushort(h2),__half_as_ushort(h3));
    ushort4 lv = make_ushort4(__half_as_ushort(l0),__half_as_ushort(l1),__half_as_ushort(l2),__half_as_ushort(l3));
    *(ushort4*)(khi + dst) = hv;
    *(ushort4*)(klo + dst) = lv;
}

// =================== V prep: qkv V-part -> transposed vthi/vtlo [b,h,d,s] half ===================
__global__ __launch_bounds__(256)
void prep_vt(const float* __restrict__ qkv, __half* __restrict__ vthi, __half* __restrict__ vtlo)
{
    __shared__ float tile[32][33];
    const int tx = threadIdx.x, ty = threadIdx.y;
    const int s0 = blockIdx.x * 32, d0 = blockIdx.y * 32;
    const int bh = blockIdx.z;                       // b*NHEAD + h
    const int b = bh / NHEAD, h = bh - b * NHEAD;
    #pragma unroll
    for (int r = 0; r < 4; r++) {
        int s = s0 + ty + r*8;
        tile[ty + r*8][tx] = qkv[((size_t)(b*SEQ + s)) * (3*NSTATE) + 2*NSTATE + h*64 + d0 + tx];
    }
    __syncthreads();
    #pragma unroll
    for (int r = 0; r < 4; r++) {
        int d = d0 + ty + r*8;
        float v = tile[tx][ty + r*8];
        __half hi, lo; split1h(v, hi, lo);
        size_t dst = ((size_t)(bh*DHEAD + d)) * SEQ + s0 + tx;
        vthi[dst] = hi;
        vtlo[dst] = lo;
    }
}

// =================== memory-KV prep (tiny, zero-padded to 128 slots) ===================
__global__ __launch_bounds__(256)
void prep_m(const float* __restrict__ mkv,
            __half* __restrict__ mkhi, __half* __restrict__ mklo,
            __half* __restrict__ mvthi, __half* __restrict__ mvtlo)
{
    int idx = blockIdx.x * 256 + threadIdx.x;        // over NHEAD*MPAD*DHEAD
    if (idx >= NHEAD*MPAD*DHEAD) return;
    int h = idx / (MPAD*DHEAD);
    int r = idx - h * (MPAD*DHEAD);
    int slot = r >> 6, d = r & 63;
    float kvl = (slot < MSLOTS) ? mkv[(size_t)slot * (2*NSTATE) + h*64 + d] : 0.f;
    float vvl = (slot < MSLOTS) ? mkv[(size_t)slot * (2*NSTATE) + NSTATE + h*64 + d] : 0.f;
    __half khf, klf, vhf, vlf;
    split1h(kvl, khf, klf);
    split1h(vvl, vhf, vlf);
    mkhi[(size_t)(h*MPAD + slot)*DHEAD + d] = khf;
    mklo[(size_t)(h*MPAD + slot)*DHEAD + d] = klf;
    mvthi[(size_t)(h*DHEAD + d)*MPAD + slot] = vhf;
    mvtlo[(size_t)(h*DHEAD + d)*MPAD + slot] = vlf;
}

// =================== mma.sync tf32 GEMM, cvt hoisted to STS time (R11, verified) ===================
template<int MODE>
__global__ __launch_bounds__(256)
void gemm_mma(const float* __restrict__ A, const float* __restrict__ A2,
              const float* __restrict__ Bt, const float* __restrict__ bias,
              float* __restrict__ C, const float* __restrict__ ea, const float* __restrict__ eb,
              int M, int N, int K, int lda, int ksplit)
{
    extern __shared__ char smem[];
    uint32_t* usm = (uint32_t*)smem;
    const int tid = threadIdx.x;
    const int w = tid >> 5, lane = tid & 31;
    const int lr = lane >> 2, kc = lane & 3;
    const int warp_m = (w >> 2) * 64;
    const int warp_n = (w & 3) * 32;
    const int row0 = blockIdx.y * 128, col0 = blockIdx.x * 128;

    const int T = K >> 5;
    const int arow = tid >> 1;
    const int acol0 = (tid & 1) * 16;
    const bool aval = (row0 + arow) < M;

    float4 pa[4], pb[4];
    auto ldg = [&](int t){
        int k0 = t * 32;
        const float* As; int ka;
        if (MODE == 1 && k0 >= ksplit) { As = A2; ka = k0 - ksplit; } else { As = A; ka = k0; }
        const float* asrc = As + (size_t)(row0 + arow) * lda + ka + acol0;
        const float* bsrc = Bt + (size_t)(col0 + arow) * K + k0 + acol0;
        #pragma unroll
        for (int j = 0; j < 4; j++) {
            pa[j] = aval ? *(const float4*)(asrc + 4*j) : make_float4(0.f,0.f,0.f,0.f);
            pb[j] = *(const float4*)(bsrc + 4*j);
        }
    };
    auto sts = [&](int b){
        uint32_t* da = usm + b * 4608 + arow * 36 + acol0;
        uint32_t* db = usm + 9216 + b * 4608 + arow * 36 + acol0;
        #pragma unroll
        for (int j = 0; j < 4; j++) {
            *(uint4*)(da + 4*j) = make_uint4(f2tf32(pa[j].x), f2tf32(pa[j].y), f2tf32(pa[j].z), f2tf32(pa[j].w));
            *(uint4*)(db + 4*j) = make_uint4(f2tf32(pb[j].x), f2tf32(pb[j].y), f2tf32(pb[j].z), f2tf32(pb[j].w));
        }
    };

    float acc[4][4][4];
    #pragma unroll
    for (int i = 0; i < 4; i++)
        #pragma unroll
        for (int j = 0; j < 4; j++)
            #pragma unroll
            for (int r = 0; r < 4; r++) acc[i][j][r] = 0.f;

    ldg(0); sts(0);
    if (T > 1) ldg(1);
    __syncthreads();

    for (int t = 0; t < T; ++t) {
        int b = t & 1;
        const uint32_t* Asb = usm + b * 4608;
        const uint32_t* Bsb = usm + 9216 + b * 4608;
        #pragma unroll
        for (int ks = 0; ks < 4; ks++) {
            const int kbase = ks * 8 + kc;
            uint32_t af[4][4], bf[4][2];
            #pragma unroll
            for (int i = 0; i < 4; i++) {
                int r0 = (warp_m + i * 16 + lr) * 36;
                af[i][0] = Asb[r0 + kbase];
                af[i][1] = Asb[r0 + 8*36 + kbase];
                af[i][2] = Asb[r0 + kbase + 4];
                af[i][3] = Asb[r0 + 8*36 + kbase + 4];
            }
            #pragma unroll
            for (int j = 0; j < 4; j++) {
                int r0 = (warp_n + j * 8 + lr) * 36;
                bf[j][0] = Bsb[r0 + kbase];
                bf[j][1] = Bsb[r0 + kbase + 4];
            }
            #pragma unroll
            for (int i = 0; i < 4; i++)
                #pragma unroll
                for (int j = 0; j < 4; j++)
                    mma_tf32(acc[i][j], af[i], bf[j]);
        }
        if (t + 1 < T) {
            sts(b ^ 1);
            if (t + 2 < T) ldg(t + 2);
        }
        __syncthreads();
    }

    float* st = (float*)smem;    // 128 x 132 floats
    #pragma unroll
    for (int i = 0; i < 4; i++) {
        #pragma unroll
        for (int j = 0; j < 4; j++) {
            int row = warp_m + i * 16 + lr;
            int col = warp_n + j * 8 + 2 * kc;
            *(float2*)&st[row * 132 + col]       = make_float2(acc[i][j][0], acc[i][j][1]);
            *(float2*)&st[(row + 8) * 132 + col] = make_float2(acc[i][j][2], acc[i][j][3]);
        }
    }
    __syncthreads();
    {
        int r  = tid >> 1;
        int ch = (tid & 1) * 64;
        int grow = row0 + r;
        if (grow < M) {
            #pragma unroll
            for (int c4 = 0; c4 < 16; c4++) {
                int col = ch + c4 * 4;
                float4 v  = *(float4*)&st[r * 132 + col];
                float4 bv = *(const float4*)(bias + col0 + col);
                v.x += bv.x; v.y += bv.y; v.z += bv.z; v.w += bv.w;
                size_t idx = (size_t)grow * N + col0 + col;
                if (MODE == 1) {
                    float4 av  = *(const float4*)(ea + idx);
                    float4 a1v = *(const float4*)(eb + idx);
                    float4 o; float al;
                    al = 1.f/(1.f + __expf(-v.x)); o.x = a1v.x + al*(av.x - a1v.x);
                    al = 1.f/(1.f + __expf(-v.y)); o.y = a1v.y + al*(av.y - a1v.y);
                    al = 1.f/(1.f + __expf(-v.z)); o.z = a1v.z + al*(av.z - a1v.z);
                    al = 1.f/(1.f + __expf(-v.w)); o.w = a1v.w + al*(av.w - a1v.w);
                    *(float4*)(C + idx) = o;
                } else {
                    *(float4*)(C + idx) = v;
                }
            }
        }
    }
}

// =================== fp16 split-3 flash attention, DOUBLE-BUFFERED cp.async pipeline ===================
// 128 q-rows/CTA, 8 warps x 16 q-rows, 64-key chunks. NO 1/sqrt(d) scaling.
// Two smem stages of 36864B (4 tiles x [64][36] words each). Prefetch t+1 during compute of t.
// QK D-frag feeds PV A-frag directly (FA2 identity) — no shuffles.
__global__ __launch_bounds__(256, 2)
void attn_h16(const float* __restrict__ qbase,
              const __half* __restrict__ khi, const __half* __restrict__ klo,
              const __half* __restrict__ vthi, const __half* __restrict__ vtlo,
              float* __restrict__ outbuf,
              int kv_len, int kslots, int q_stride, long long q_bstride, int kv_batched)
{
    extern __shared__ uint32_t sm4[];
    const uint32_t sb = smem_u32(sm4);

    const int tid = threadIdx.x;
    const int w = tid >> 5, lane = tid & 31;
    const int lr = lane >> 2, kc = lane & 3;
    const int h = blockIdx.y, b = blockIdx.z;
    const int q0 = blockIdx.x * 128;
    const float* qb = qbase + (size_t)b * q_bstride + h * 64;
    const int bh = kv_batched * b * NHEAD + h;
    const __half* kbh = khi  + (size_t)bh * kslots * DHEAD;
    const __half* kbl = klo  + (size_t)bh * kslots * DHEAD;
    const __half* vbh = vthi + (size_t)bh * DHEAD * kslots;
    const __half* vbl = vtlo + (size_t)bh * DHEAD * kslots;

    const int qrow0 = q0 + w * 16 + lr;

    // persistent Q fragments (fp16 hi/lo), chunk c covers d = 16c..16c+15
    uint32_t Qh[4][4], Ql[4][4];
    {
        const float* r0p = qb + (size_t)qrow0 * q_stride;
        const float* r1p = qb + (size_t)(qrow0 + 8) * q_stride;
        #pragma unroll
        for (int c = 0; c < 4; c++) {
            int d0 = c * 16 + 2 * kc;
            float2 v00 = *(const float2*)(r0p + d0);
            float2 v10 = *(const float2*)(r1p + d0);
            float2 v01 = *(const float2*)(r0p + d0 + 8);
            float2 v11 = *(const float2*)(r1p + d0 + 8);
            split2h(v00.x, v00.y, Qh[c][0], Ql[c][0]);
            split2h(v10.x, v10.y, Qh[c][1], Ql[c][1]);
            split2h(v01.x, v01.y, Qh[c][2], Ql[c][2]);
            split2h(v11.x, v11.y, Qh[c][3], Ql[c][3]);
        }
    }

    float m0 = -1e30f, m1 = -1e30f, l0 = 0.f, l1 = 0.f;
    float O[8][4];
    #pragma unroll
    for (int d = 0; d < 8; d++) { O[d][0]=0.f; O[d][1]=0.f; O[d][2]=0.f; O[d][3]=0.f; }

    // per-thread loader coordinates: row 0..63, two 16B chunks of 8 per row
    const int ldrow = tid >> 2;
    const int ldseg = (tid & 3) * 2;
    const uint32_t soff = (uint32_t)ldrow * 144u + (uint32_t)ldseg * 16u;

    auto prefetch = [&](int t, int stg){
        const uint32_t s0 = sb + (uint32_t)stg * 36864u;
        size_t goff = ((size_t)(t*64 + ldrow)) * DHEAD + ldseg * 8;   // halves
        size_t voff = ((size_t)ldrow) * kslots + (size_t)t*64 + ldseg * 8;
        cp16h(s0 + soff,                    kbh + goff);
        cp16h(s0 + soff + 16,               kbh + goff + 8);
        cp16h(s0 + 9216u  + soff,           kbl + goff);
        cp16h(s0 + 9216u  + soff + 16,      kbl + goff + 8);
        cp16h(s0 + 18432u + soff,           vbh + voff);
        cp16h(s0 + 18432u + soff + 16,      vbh + voff + 8);
        cp16h(s0 + 27648u + soff,           vbl + voff);
        cp16h(s0 + 27648u + soff + 16,      vbl + voff + 8);
        cp_commit();
    };

    const int nkb = (kv_len + 63) >> 6;
    prefetch(0, 0);

    for (int t = 0; t < nkb; ++t) {
        const int stg = t & 1;
        if (t + 1 < nkb) { prefetch(t + 1, stg ^ 1); cp_wait<1>(); }
        else             { cp_wait<0>(); }
        __syncthreads();   // stage stg fully loaded, visible to all

        const uint32_t* Khi = sm4 + stg * 9216;
        const uint32_t* Klo = Khi + 64*36;
        const uint32_t* Vhi = Khi + 2*64*36;
        const uint32_t* Vlo = Khi + 3*64*36;

        // ---- S = Q K^T (fp16 split-3) ----
        float sD[8][4];
        #pragma unroll
        for (int nt = 0; nt < 8; nt++) {
            float d4[4] = {0.f, 0.f, 0.f, 0.f};
            const int base = (8*nt + lr) * 36 + kc;
            #pragma unroll
            for (int c = 0; c < 4; c++) {
                uint32_t bh2[2], bl2[2];
                bh2[0] = Khi[base + 8*c];  bh2[1] = Khi[base + 8*c + 4];
                bl2[0] = Klo[base + 8*c];  bl2[1] = Klo[base + 8*c + 4];
                mma_f16(d4, Qh[c], bh2);
                mma_f16(d4, Ql[c], bh2);
                mma_f16(d4, Qh[c], bl2);
            }
            sD[nt][0]=d4[0]; sD[nt][1]=d4[1]; sD[nt][2]=d4[2]; sD[nt][3]=d4[3];
        }

        // ---- mask partial chunk ----
        int rem = kv_len - t * 64;
        if (rem < 64) {
            #pragma unroll
            for (int nt = 0; nt < 8; nt++) {
                int k0e = 8*nt + 2*kc;
                if (k0e     >= rem) { sD[nt][0] = -1e30f; sD[nt][2] = -1e30f; }
                if (k0e + 1 >= rem) { sD[nt][1] = -1e30f; sD[nt][3] = -1e30f; }
            }
        }

        // ---- online softmax (register + quad-shfl) ----
        float rm0 = -1e30f, rm1 = -1e30f;
        #pragma unroll
        for (int nt = 0; nt < 8; nt++) {
            rm0 = fmaxf(rm0, fmaxf(sD[nt][0], sD[nt][1]));
            rm1 = fmaxf(rm1, fmaxf(sD[nt][2], sD[nt][3]));
        }
        rm0 = fmaxf(rm0, __shfl_xor_sync(0xffffffffu, rm0, 1));
        rm0 = fmaxf(rm0, __shfl_xor_sync(0xffffffffu, rm0, 2));
        rm1 = fmaxf(rm1, __shfl_xor_sync(0xffffffffu, rm1, 1));
        rm1 = fmaxf(rm1, __shfl_xor_sync(0xffffffffu, rm1, 2));
        float mn0 = fmaxf(m0, rm0), mn1 = fmaxf(m1, rm1);
        float sc0 = __expf(m0 - mn0), sc1 = __expf(m1 - mn1);
        m0 = mn0; m1 = mn1;
        float rs0 = 0.f, rs1 = 0.f;
        #pragma unroll
        for (int nt = 0; nt < 8; nt++) {
            sD[nt][0] = __expf(sD[nt][0] - m0);
            sD[nt][1] = __expf(sD[nt][1] - m0);
            sD[nt][2] = __expf(sD[nt][2] - m1);
            sD[nt][3] = __expf(sD[nt][3] - m1);
            rs0 += sD[nt][0] + sD[nt][1];
            rs1 += sD[nt][2] + sD[nt][3];
        }
        rs0 += __shfl_xor_sync(0xffffffffu, rs0, 1);
        rs0 += __shfl_xor_sync(0xffffffffu, rs0, 2);
        rs1 += __shfl_xor_sync(0xffffffffu, rs1, 1);
        rs1 += __shfl_xor_sync(0xffffffffu, rs1, 2);
        l0 = l0 * sc0 + rs0;
        l1 = l1 * sc1 + rs1;
        #pragma unroll
        for (int d = 0; d < 8; d++) {
            O[d][0] *= sc0; O[d][1] *= sc0; O[d][2] *= sc1; O[d][3] *= sc1;
        }

        // ---- O += P V (fp16 split-3); QK D-frag == PV A-frag layout, no shuffles ----
        #pragma unroll
        for (int c = 0; c < 4; c++) {
            uint32_t aH[4], aL[4];
            split2h(sD[2*c][0],   sD[2*c][1],   aH[0], aL[0]);
            split2h(sD[2*c][2],   sD[2*c][3],   aH[1], aL[1]);
            split2h(sD[2*c+1][0], sD[2*c+1][1], aH[2], aL[2]);
            split2h(sD[2*c+1][2], sD[2*c+1][3], aH[3], aL[3]);
            #pragma unroll
            for (int dt = 0; dt < 8; dt++) {
                const int base = (8*dt + lr) * 36 + 8*c + kc;
                uint32_t bh2[2], bl2[2];
                bh2[0] = Vhi[base];  bh2[1] = Vhi[base + 4];
                bl2[0] = Vlo[base];  bl2[1] = Vlo[base + 4];
                mma_f16(O[dt], aH, bh2);
                mma_f16(O[dt], aL, bh2);
                mma_f16(O[dt], aH, bl2);
            }
        }
        __syncthreads();   // all reads of stage stg done before iter t+1 prefetches into it
    }

    // ---- epilogue ----
    float inv0 = 1.f / l0, inv1 = 1.f / l1;
    float* op0 = outbuf + ((size_t)b * SEQ + qrow0) * NSTATE + h * 64;
    float* op1 = op0 + 8 * NSTATE;
    #pragma unroll
    for (int dt = 0; dt < 8; dt++) {
        *(float2*)(op0 + dt*8 + 2*kc) = make_float2(O[dt][0]*inv0, O[dt][1]*inv0);
        *(float2*)(op1 + dt*8 + 2*kc) = make_float2(O[dt][2]*inv1, O[dt][3]*inv1);
    }
}

// ------------------------------- launch --------------------------------------------
extern "C" void kernel_launch(void* const* d_in, const int* in_sizes, int n_in,
                              void* d_out, int out_size)
{
    const float* x       = (const float*)d_in[0];
    const float* w_attn  = (const float*)d_in[1];
    const float* b_attn  = (const float*)d_in[2];
    const float* w_proj  = (const float*)d_in[3];
    const float* b_proj  = (const float*)d_in[4];
    const float* w_mem   = (const float*)d_in[5];
    const float* b_mem   = (const float*)d_in[6];
    const float* w_alpha = (const float*)d_in[7];
    const float* b_alpha = (const float*)d_in[8];
    const float* memf    = (const float*)d_in[9];
    float* out = (float*)d_out;

    float *qkv, *mkv, *a, *a1, *fu, *wattnT, *wmemT, *walphaT, *wprojT;
    __half *khi, *klo, *vthi, *vtlo, *mkhi, *mklo, *mvthi, *mvtlo;
    cudaGetSymbolAddress((void**)&qkv, g_qkv);
    cudaGetSymbolAddress((void**)&mkv, g_mkv);
    cudaGetSymbolAddress((void**)&a,   g_a);
    cudaGetSymbolAddress((void**)&a1,  g_a1);
    cudaGetSymbolAddress((void**)&fu,  g_fused);
    cudaGetSymbolAddress((void**)&wattnT,  g_wattnT);
    cudaGetSymbolAddress((void**)&wmemT,   g_wmemT);
    cudaGetSymbolAddress((void**)&walphaT, g_walphaT);
    cudaGetSymbolAddress((void**)&wprojT,  g_wprojT);
    cudaGetSymbolAddress((void**)&khi,  g_khi);
    cudaGetSymbolAddress((void**)&klo,  g_klo);
    cudaGetSymbolAddress((void**)&vthi, g_vthi);
    cudaGetSymbolAddress((void**)&vtlo, g_vtlo);
    cudaGetSymbolAddress((void**)&mkhi,  g_mkhi);
    cudaGetSymbolAddress((void**)&mklo,  g_mklo);
    cudaGetSymbolAddress((void**)&mvthi, g_mvthi);
    cudaGetSymbolAddress((void**)&mvtlo, g_mvtlo);

    const int attn_smem = 2 * 4 * 64 * 36 * 4;   // 73728 (double-buffered)
    const int gemm_smem = 73728;
    cudaFuncSetAttribute(attn_h16, cudaFuncAttributeMaxDynamicSharedMemorySize, attn_smem);
    cudaFuncSetAttribute(gemm_mma<0>, cudaFuncAttributeMaxDynamicSharedMemorySize, gemm_smem);
    cudaFuncSetAttribute(gemm_mma<1>, cudaFuncAttributeMaxDynamicSharedMemorySize, gemm_smem);

    dim3 tb(32, 8);
    transpose_k<<<dim3(3*NSTATE/32, NSTATE/32), tb>>>(w_attn,  wattnT,  NSTATE,   3*NSTATE);
    transpose_k<<<dim3(2*NSTATE/32, NSTATE/32), tb>>>(w_mem,   wmemT,   NSTATE,   2*NSTATE);
    transpose_k<<<dim3(NSTATE/32, 2*NSTATE/32), tb>>>(w_alpha, walphaT, 2*NSTATE, NSTATE);
    transpose_k<<<dim3(NSTATE/32, NSTATE/32),   tb>>>(w_proj,  wprojT,  NSTATE,   NSTATE);

    // 1) qkv = x @ w_attn + b_attn      [4096, 2304]
    gemm_mma<0><<<dim3(3*NSTATE/128, NTOK/128), 256, gemm_smem>>>(
        x, nullptr, wattnT, b_attn, qkv, nullptr, nullptr,
        NTOK, 3*NSTATE, NSTATE, NSTATE, 0);

    // 2) mkv = mem @ w_mem + b_mem      [100, 1536]
    gemm_mma<0><<<dim3(2*NSTATE/128, 1), 256, gemm_smem>>>(
        memf, nullptr, wmemT, b_mem, mkv, nullptr, nullptr,
        MSLOTS, 2*NSTATE, NSTATE, NSTATE, 0);

    // 2b) pre-split K/V into fp16 hi/lo buffers
    prep_k<<<NTOK*NSTATE/4/256, 256>>>(qkv, khi, klo);
    prep_vt<<<dim3(SEQ/32, DHEAD/32, BSZ*NHEAD), tb>>>(qkv, vthi, vtlo);
    prep_m<<<(NHEAD*MPAD*DHEAD + 255)/256, 256>>>(mkv, mkhi, mklo, mvthi, mvtlo);

    // 3) self attention -> g_a
    attn_h16<<<dim3(SEQ/128, NHEAD, BSZ), 256, attn_smem>>>(
        qkv, khi, klo, vthi, vtlo, a,
        SEQ, SEQ, 3*NSTATE, (long long)SEQ * 3 * NSTATE, 1);

    // 4) memory attention -> g_a1 (kv shared across batch)
    attn_h16<<<dim3(SEQ/128, NHEAD, BSZ), 256, attn_smem>>>(
        qkv, mkhi, mklo, mvthi, mvtlo, a1,
        MSLOTS, MPAD, 3*NSTATE, (long long)SEQ * 3 * NSTATE, 0);

    // 5) fused = sigmoid([a|a1]@w_alpha + b_alpha) gate
    gemm_mma<1><<<dim3(NSTATE/128, NTOK/128), 256, gemm_smem>>>(
        a, a1, walphaT, b_alpha, fu, a, a1,
        NTOK, NSTATE, 2*NSTATE, NSTATE, NSTATE);

    // 6) out = fused @ w_proj + b_proj
    gemm_mma<0><<<dim3(NSTATE/128, NTOK/128), 256, gemm_smem>>>(
        fu, nullptr, wprojT, b_proj, out, nullptr, nullptr,
        NTOK, NSTATE, NSTATE, NSTATE, 0);
}